// round 2
// baseline (speedup 1.0000x reference)
#include <cuda_runtime.h>

#define N_CUST 500000
#define N_FUND 50000
#define N_EDGE 4000000
#define D_CUST 101
#define HID 64
#define TM 128          // customers per block
#define SX_STRIDE 27    // odd stride -> conflict-free shared x

// ---- device scratch (no allocations allowed) ----
__device__ float g_sum[N_CUST * 2];   // per-customer projected neighbor sum (2 dims)
__device__ float g_cnt[N_CUST];       // per-customer edge count
__device__ float g_gf[N_FUND * 2];    // per-fund projected features: relu(xf*Wf+bf) @ A2
__device__ float g_A2[HID * 2];       // W_l @ W_out
__device__ float g_B2[HID * 2];       // W_r @ W_out
__device__ float g_c2[2];             // b_l @ W_out + b_out

// ---------------------------------------------------------------
// Fold the linear head into the two 64-dim branches.
// ---------------------------------------------------------------
__global__ void combine_weights_kernel(const float* __restrict__ W_l,
                                       const float* __restrict__ b_l,
                                       const float* __restrict__ W_r,
                                       const float* __restrict__ W_out,
                                       const float* __restrict__ b_out) {
    int t = threadIdx.x;
    if (t < HID * 2) {
        int k = t >> 1, j = t & 1;
        float a = 0.f, b = 0.f;
        #pragma unroll
        for (int h = 0; h < HID; h++) {
            a += W_l[k * HID + h] * W_out[h * 2 + j];
            b += W_r[k * HID + h] * W_out[h * 2 + j];
        }
        g_A2[k * 2 + j] = a;
        g_B2[k * 2 + j] = b;
    }
    if (t < 2) {
        float c = b_out[t];
        #pragma unroll
        for (int h = 0; h < HID; h++) c += b_l[h] * W_out[h * 2 + t];
        g_c2[t] = c;
    }
}

// ---------------------------------------------------------------
// Zero accumulators.
// ---------------------------------------------------------------
__global__ void zero_kernel() {
    int i = blockIdx.x * blockDim.x + threadIdx.x;
    if (i < N_CUST * 2) g_sum[i] = 0.f;
    if (i < N_CUST) g_cnt[i] = 0.f;
}

// ---------------------------------------------------------------
// Per-fund: g_f = relu(x_f * W_fund + b_fund) @ A2   -> [N_FUND, 2]
// ---------------------------------------------------------------
__global__ void fund_kernel(const float* __restrict__ x_fund,
                            const float* __restrict__ W_fund,
                            const float* __restrict__ b_fund) {
    __shared__ float sw[HID];
    __shared__ float sb[HID];
    __shared__ float sA[HID * 2];
    int t = threadIdx.x;
    if (t < HID) { sw[t] = W_fund[t]; sb[t] = b_fund[t]; }
    if (t < HID * 2) sA[t] = g_A2[t];
    __syncthreads();

    int j = blockIdx.x * blockDim.x + t;
    if (j >= N_FUND) return;
    float xv = x_fund[j];
    float a0 = 0.f, a1 = 0.f;
    #pragma unroll
    for (int h = 0; h < HID; h++) {
        float hv = fmaxf(xv * sw[h] + sb[h], 0.f);
        a0 += hv * sA[h * 2 + 0];
        a1 += hv * sA[h * 2 + 1];
    }
    reinterpret_cast<float2*>(g_gf)[j] = make_float2(a0, a1);
}

// ---------------------------------------------------------------
// Edge scatter: only 2 floats + count per edge (projection done up front).
// Indices are int32 (JAX without x64 coerces int64 -> int32).
// ---------------------------------------------------------------
__global__ void edge_kernel(const int* __restrict__ src,
                            const int* __restrict__ dst) {
    int i = blockIdx.x * blockDim.x + threadIdx.x;
    if (i >= N_EDGE) return;
    int s = __ldg(&src[i]);
    int d = __ldg(&dst[i]);
    float2 g = reinterpret_cast<const float2*>(g_gf)[s];
    atomicAdd(&g_sum[2 * d + 0], g.x);
    atomicAdd(&g_sum[2 * d + 1], g.y);
    atomicAdd(&g_cnt[d], 1.0f);
}

// ---------------------------------------------------------------
// Customer kernel: h = relu(x @ W_cust + b_cust);
// out = g_sum/max(cnt,1) + h @ B2 + c2
// W_cust in SMEM, x staged in K-chunks; packed f32x2 FMA mainloop.
// ---------------------------------------------------------------
__global__ void __launch_bounds__(TM) cust_kernel(const float* __restrict__ x,
                                                  const float* __restrict__ W_cust,
                                                  const float* __restrict__ b_cust,
                                                  float* __restrict__ out) {
    __shared__ __align__(16) float sW[D_CUST * HID];   // 25856 B, [k][h] row-major
    __shared__ float sx[TM * SX_STRIDE];               // 13824 B
    __shared__ float sB2[HID * 2];
    __shared__ float sbc[HID];

    const int tid = threadIdx.x;
    const int base = blockIdx.x * TM;

    for (int i = tid; i < D_CUST * HID; i += TM) sW[i] = W_cust[i];
    if (tid < HID * 2) sB2[tid] = g_B2[tid];
    if (tid < HID) sbc[tid] = b_cust[tid];
    __syncthreads();

    // 32 packed accumulators: acc2[j] holds hidden units (2j, 2j+1)
    unsigned long long acc2[32];
    #pragma unroll
    for (int j = 0; j < 32; j++) {
        float lo = sbc[2 * j], hi = sbc[2 * j + 1];
        asm("mov.b64 %0, {%1, %2};" : "=l"(acc2[j]) : "f"(lo), "f"(hi));
    }

    const unsigned sW_base = (unsigned)__cvta_generic_to_shared(sW);
    const int kstart[5] = {0, 26, 51, 76, 101};

    for (int ci = 0; ci < 4; ci++) {
        const int k0 = kstart[ci];
        const int ck = kstart[ci + 1] - k0;
        __syncthreads();   // previous chunk consumed
        // stage x tile (coalesced-ish: contiguous per-row segments)
        const int n_elems = TM * ck;
        for (int idx = tid; idx < n_elems; idx += TM) {
            int r = idx / ck;
            int c = idx - r * ck;
            int row = base + r;
            sx[r * SX_STRIDE + c] =
                (row < N_CUST) ? x[row * D_CUST + k0 + c] : 0.f;
        }
        __syncthreads();

        for (int kk = 0; kk < ck; kk++) {
            float xv = sx[tid * SX_STRIDE + kk];
            unsigned long long xv2;
            asm("mov.b64 %0, {%1, %1};" : "=l"(xv2) : "f"(xv));
            unsigned addr = sW_base + (unsigned)((k0 + kk) * (HID * 4));
            #pragma unroll
            for (int j = 0; j < 16; j++) {
                unsigned long long w0, w1;
                asm("ld.shared.v2.b64 {%0, %1}, [%2];"
                    : "=l"(w0), "=l"(w1) : "r"(addr + j * 16));
                asm("fma.rn.f32x2 %0, %1, %2, %0;" : "+l"(acc2[2 * j])     : "l"(w0), "l"(xv2));
                asm("fma.rn.f32x2 %0, %1, %2, %0;" : "+l"(acc2[2 * j + 1]) : "l"(w1), "l"(xv2));
            }
        }
    }

    const int c = base + tid;
    if (c < N_CUST) {
        float o0 = 0.f, o1 = 0.f;
        #pragma unroll
        for (int j = 0; j < 32; j++) {
            float lo, hi;
            asm("mov.b64 {%0, %1}, %2;" : "=f"(lo), "=f"(hi) : "l"(acc2[j]));
            lo = fmaxf(lo, 0.f);
            hi = fmaxf(hi, 0.f);
            o0 += lo * sB2[(2 * j) * 2 + 0] + hi * sB2[(2 * j + 1) * 2 + 0];
            o1 += lo * sB2[(2 * j) * 2 + 1] + hi * sB2[(2 * j + 1) * 2 + 1];
        }
        float cnt = fmaxf(g_cnt[c], 1.0f);
        float inv = 1.0f / cnt;
        float2 s = reinterpret_cast<const float2*>(g_sum)[c];
        float2 r;
        r.x = s.x * inv + o0 + g_c2[0];
        r.y = s.y * inv + o1 + g_c2[1];
        reinterpret_cast<float2*>(out)[c] = r;
    }
}

// ---------------------------------------------------------------
// Launch
// ---------------------------------------------------------------
extern "C" void kernel_launch(void* const* d_in, const int* in_sizes, int n_in,
                              void* d_out, int out_size) {
    const float* x_customer = (const float*)d_in[0];
    const float* x_fund     = (const float*)d_in[1];
    const int*   src_fund   = (const int*)d_in[2];
    const int*   dst_cust   = (const int*)d_in[3];
    const float* W_cust     = (const float*)d_in[4];
    const float* b_cust     = (const float*)d_in[5];
    const float* W_fund     = (const float*)d_in[6];
    const float* b_fund     = (const float*)d_in[7];
    const float* W_l        = (const float*)d_in[8];
    const float* b_l        = (const float*)d_in[9];
    const float* W_r        = (const float*)d_in[10];
    const float* W_out      = (const float*)d_in[11];
    const float* b_out      = (const float*)d_in[12];
    float* out = (float*)d_out;

    combine_weights_kernel<<<1, 128>>>(W_l, b_l, W_r, W_out, b_out);

    {
        int n = N_CUST * 2;
        int blocks = (n + 255) / 256;
        zero_kernel<<<blocks, 256>>>();
    }

    {
        int blocks = (N_FUND + 255) / 256;
        fund_kernel<<<blocks, 256>>>(x_fund, W_fund, b_fund);
    }

    {
        int blocks = (N_EDGE + 255) / 256;
        edge_kernel<<<blocks, 256>>>(src_fund, dst_cust);
    }

    {
        int blocks = (N_CUST + TM - 1) / TM;
        cust_kernel<<<blocks, TM>>>(x_customer, W_cust, b_cust, out);
    }
}

// round 3
// speedup vs baseline: 1.1887x; 1.1887x over previous
#include <cuda_runtime.h>

#define N_CUST 500000
#define N_FUND 50000
#define N_EDGE 4000000
#define D_CUST 101
#define HID 64
#define KPAD 104                 // D_CUST padded to multiple of 4
#define TM 128                   // customers per block
#define CUST_THREADS 128

// dynamic smem layout (bytes)
#define SW_OFF  0                           // [KPAD][64] floats = 26624 B
#define SX_OFF  (KPAD * HID * 4)            // 26624 (128B aligned): [128][KPAD] swizzled = 53248 B
#define SB2_OFF (SX_OFF + TM * KPAD * 4)    // 79872: 128 floats = 512 B
#define SMEM_TOTAL (SB2_OFF + 512)          // 80384 B

// ---- device scratch (no allocations allowed) ----
__device__ float4 g_acc[N_CUST];      // {sum0, sum1, count, pad} per customer
__device__ float  g_gf[N_FUND * 2];   // per-fund projected features
__device__ float  g_A2[HID * 2];      // W_l @ W_out
__device__ float  g_B2[HID * 2];      // W_r @ W_out
__device__ float  g_c2[2];            // b_l @ W_out + b_out

// ---------------------------------------------------------------
// Fold the linear head into the two 64-dim branches.
// ---------------------------------------------------------------
__global__ void combine_weights_kernel(const float* __restrict__ W_l,
                                       const float* __restrict__ b_l,
                                       const float* __restrict__ W_r,
                                       const float* __restrict__ W_out,
                                       const float* __restrict__ b_out) {
    int t = threadIdx.x;
    if (t < HID * 2) {
        int k = t >> 1, j = t & 1;
        float a = 0.f, b = 0.f;
        #pragma unroll
        for (int h = 0; h < HID; h++) {
            a += W_l[k * HID + h] * W_out[h * 2 + j];
            b += W_r[k * HID + h] * W_out[h * 2 + j];
        }
        g_A2[k * 2 + j] = a;
        g_B2[k * 2 + j] = b;
    }
    if (t < 2) {
        float c = b_out[t];
        #pragma unroll
        for (int h = 0; h < HID; h++) c += b_l[h] * W_out[h * 2 + t];
        g_c2[t] = c;
    }
}

// ---------------------------------------------------------------
// Zero accumulators (float4 stores).
// ---------------------------------------------------------------
__global__ void zero_kernel() {
    int i = blockIdx.x * blockDim.x + threadIdx.x;
    if (i < N_CUST) g_acc[i] = make_float4(0.f, 0.f, 0.f, 0.f);
}

// ---------------------------------------------------------------
// Per-fund: g_f = relu(x_f * W_fund + b_fund) @ A2   -> [N_FUND, 2]
// ---------------------------------------------------------------
__global__ void fund_kernel(const float* __restrict__ x_fund,
                            const float* __restrict__ W_fund,
                            const float* __restrict__ b_fund) {
    __shared__ float sw[HID];
    __shared__ float sb[HID];
    __shared__ float sA[HID * 2];
    int t = threadIdx.x;
    if (t < HID) { sw[t] = W_fund[t]; sb[t] = b_fund[t]; }
    if (t < HID * 2) sA[t] = g_A2[t];
    __syncthreads();

    int j = blockIdx.x * blockDim.x + t;
    if (j >= N_FUND) return;
    float xv = x_fund[j];
    float a0 = 0.f, a1 = 0.f;
    #pragma unroll
    for (int h = 0; h < HID; h++) {
        float hv = fmaxf(xv * sw[h] + sb[h], 0.f);
        a0 += hv * sA[h * 2 + 0];
        a1 += hv * sA[h * 2 + 1];
    }
    reinterpret_cast<float2*>(g_gf)[j] = make_float2(a0, a1);
}

// ---------------------------------------------------------------
// Edge scatter: one 16B vector reduction per edge.
// ---------------------------------------------------------------
__global__ void edge_kernel(const int* __restrict__ src,
                            const int* __restrict__ dst) {
    int i = blockIdx.x * blockDim.x + threadIdx.x;
    if (i >= N_EDGE) return;
    int s = __ldg(&src[i]);
    int d = __ldg(&dst[i]);
    float2 g = reinterpret_cast<const float2*>(g_gf)[s];
    float4* p = &g_acc[d];
    asm volatile("red.global.add.v4.f32 [%0], {%1, %2, %3, %4};"
                 :: "l"(p), "f"(g.x), "f"(g.y), "f"(1.0f), "f"(0.0f)
                 : "memory");
}

// ---------------------------------------------------------------
// Customer kernel: register-tiled SGEMM (8M x 8N per thread) with
// packed f32x2 FMA; fused ReLU + head projection + SAGE combine.
// ---------------------------------------------------------------
__global__ void __launch_bounds__(CUST_THREADS)
cust_kernel(const float* __restrict__ x,
            const float* __restrict__ W_cust,
            const float* __restrict__ b_cust,
            float* __restrict__ out) {
    extern __shared__ char dsm[];
    float* sW  = reinterpret_cast<float*>(dsm + SW_OFF);
    float* sB2 = reinterpret_cast<float*>(dsm + SB2_OFF);

    const int tid  = threadIdx.x;
    const int base = blockIdx.x * TM;
    const int tm   = tid & 15;          // 16 m-groups
    const int tn   = tid >> 4;          // 8 n-groups
    const int m0   = tm * 8;
    const int n0   = tn * 8;

    // --- stage W [101][64] -> sW [104][64], pad rows zeroed ---
    for (int idx = tid; idx < KPAD * HID; idx += CUST_THREADS)
        sW[idx] = (idx < D_CUST * HID) ? W_cust[idx] : 0.f;
    if (tid < HID * 2) sB2[tid] = g_B2[tid];

    // --- stage x [128][104] swizzled: warp handles rows, lanes along k ---
    {
        int lane = tid & 31, w4 = tid >> 5;
        for (int m = w4; m < TM; m += 4) {
            int row = base + m;
            const float* xr = x + (long long)row * D_CUST;
            unsigned rowoff = SX_OFF + (unsigned)m * (KPAD * 4);
            unsigned C = ((unsigned)(m >> 3) & 7u) << 4;
            #pragma unroll
            for (int kc = 0; kc < 4; kc++) {
                int k = lane + kc * 32;
                if (k < KPAD) {
                    float v = (row < N_CUST && k < D_CUST) ? xr[k] : 0.f;
                    *reinterpret_cast<float*>(dsm + ((rowoff + k * 4) ^ C)) = v;
                }
            }
        }
    }
    __syncthreads();

    // --- accumulators: acc2[i][j] = hidden pair (n0+2j, n0+2j+1) of row m0+i ---
    unsigned long long acc2[8][4];
    {
        unsigned long long b2[4];
        #pragma unroll
        for (int j = 0; j < 4; j++) {
            float lo = b_cust[n0 + 2 * j], hi = b_cust[n0 + 2 * j + 1];
            asm("mov.b64 %0, {%1, %2};" : "=l"(b2[j]) : "f"(lo), "f"(hi));
        }
        #pragma unroll
        for (int i = 0; i < 8; i++)
            #pragma unroll
            for (int j = 0; j < 4; j++) acc2[i][j] = b2[j];
    }

    const unsigned swbase = (unsigned)__cvta_generic_to_shared(dsm);
    const unsigned Cme = ((unsigned)tm & 7u) << 4;   // swizzle const for this thread's rows

    // --- mainloop: 26 chunks of 4 k ---
    for (int k0 = 0; k0 < KPAD; k0 += 4) {
        // x registers: 8 rows x float4
        float4 xq[8];
        #pragma unroll
        for (int i = 0; i < 8; i++) {
            unsigned off = SX_OFF + (unsigned)(m0 + i) * (KPAD * 4) + (unsigned)k0 * 4;
            xq[i] = *reinterpret_cast<const float4*>(dsm + (off ^ Cme));
        }
        #pragma unroll
        for (int k = 0; k < 4; k++) {
            unsigned waddr = swbase + (unsigned)(k0 + k) * (HID * 4) + (unsigned)n0 * 4;
            unsigned long long wp0, wp1, wp2, wp3;
            asm("ld.shared.v2.b64 {%0, %1}, [%2];" : "=l"(wp0), "=l"(wp1) : "r"(waddr));
            asm("ld.shared.v2.b64 {%0, %1}, [%2];" : "=l"(wp2), "=l"(wp3) : "r"(waddr + 16));
            #pragma unroll
            for (int i = 0; i < 8; i++) {
                float xv = (k == 0) ? xq[i].x : (k == 1) ? xq[i].y : (k == 2) ? xq[i].z : xq[i].w;
                unsigned long long xv2;
                asm("mov.b64 %0, {%1, %1};" : "=l"(xv2) : "f"(xv));
                asm("fma.rn.f32x2 %0, %1, %2, %0;" : "+l"(acc2[i][0]) : "l"(wp0), "l"(xv2));
                asm("fma.rn.f32x2 %0, %1, %2, %0;" : "+l"(acc2[i][1]) : "l"(wp1), "l"(xv2));
                asm("fma.rn.f32x2 %0, %1, %2, %0;" : "+l"(acc2[i][2]) : "l"(wp2), "l"(xv2));
                asm("fma.rn.f32x2 %0, %1, %2, %0;" : "+l"(acc2[i][3]) : "l"(wp3), "l"(xv2));
            }
        }
    }

    // --- epilogue: relu + partial head projection, reduce across tn ---
    __syncthreads();                          // done reading sX/sW
    float* sRed = reinterpret_cast<float*>(dsm);   // reuse sW region: [128][8][2]
    #pragma unroll
    for (int i = 0; i < 8; i++) {
        float o0 = 0.f, o1 = 0.f;
        #pragma unroll
        for (int j = 0; j < 4; j++) {
            float lo, hi;
            asm("mov.b64 {%0, %1}, %2;" : "=f"(lo), "=f"(hi) : "l"(acc2[i][j]));
            lo = fmaxf(lo, 0.f);
            hi = fmaxf(hi, 0.f);
            int n = n0 + 2 * j;
            o0 += lo * sB2[2 * n]     + hi * sB2[2 * n + 2];
            o1 += lo * sB2[2 * n + 1] + hi * sB2[2 * n + 3];
        }
        sRed[(m0 + i) * 16 + tn * 2 + 0] = o0;
        sRed[(m0 + i) * 16 + tn * 2 + 1] = o1;
    }
    __syncthreads();

    // --- final: one thread per customer row ---
    {
        int row = base + tid;
        if (row < N_CUST) {
            float t0 = g_c2[0], t1 = g_c2[1];
            #pragma unroll
            for (int q = 0; q < 8; q++) {
                t0 += sRed[tid * 16 + q * 2 + 0];
                t1 += sRed[tid * 16 + q * 2 + 1];
            }
            float4 a = g_acc[row];
            float inv = 1.0f / fmaxf(a.z, 1.0f);
            reinterpret_cast<float2*>(out)[row] =
                make_float2(a.x * inv + t0, a.y * inv + t1);
        }
    }
}

// ---------------------------------------------------------------
// Launch
// ---------------------------------------------------------------
extern "C" void kernel_launch(void* const* d_in, const int* in_sizes, int n_in,
                              void* d_out, int out_size) {
    const float* x_customer = (const float*)d_in[0];
    const float* x_fund     = (const float*)d_in[1];
    const int*   src_fund   = (const int*)d_in[2];
    const int*   dst_cust   = (const int*)d_in[3];
    const float* W_cust     = (const float*)d_in[4];
    const float* b_cust     = (const float*)d_in[5];
    const float* W_fund     = (const float*)d_in[6];
    const float* b_fund     = (const float*)d_in[7];
    const float* W_l        = (const float*)d_in[8];
    const float* b_l        = (const float*)d_in[9];
    const float* W_r        = (const float*)d_in[10];
    const float* W_out      = (const float*)d_in[11];
    const float* b_out      = (const float*)d_in[12];
    float* out = (float*)d_out;

    cudaFuncSetAttribute(cust_kernel,
                         cudaFuncAttributeMaxDynamicSharedMemorySize, SMEM_TOTAL);

    combine_weights_kernel<<<1, 128>>>(W_l, b_l, W_r, W_out, b_out);

    zero_kernel<<<(N_CUST + 255) / 256, 256>>>();

    fund_kernel<<<(N_FUND + 255) / 256, 256>>>(x_fund, W_fund, b_fund);

    edge_kernel<<<(N_EDGE + 255) / 256, 256>>>(src_fund, dst_cust);

    cust_kernel<<<(N_CUST + TM - 1) / TM, CUST_THREADS, SMEM_TOTAL>>>(
        x_customer, W_cust, b_cust, out);
}

// round 5
// speedup vs baseline: 2.1027x; 1.7689x over previous
#include <cuda_runtime.h>
#include <cuda_bf16.h>
#include <cstdint>

#define N_CUST 500000
#define N_FUND 50000
#define N_EDGE 4000000
#define D_CUST 101
#define HID 64
#define KP 120                    // padded K (stride 240B -> conflict-free ldmatrix)
#define TM 128                    // rows per block tile
#define CT 256                    // threads per block

// smem byte offsets
#define SM_AH 0
#define SM_AL (SM_AH + TM * KP * 2)          // 30720
#define SM_BH (SM_AL + TM * KP * 2)          // 61440
#define SM_BL (SM_BH + HID * KP * 2)         // 76800
#define SM_B2 (SM_BL + HID * KP * 2)         // 92160 : 128 floats
#define SM_BC (SM_B2 + 512)                  // 92672 : 64 floats
#define SM_TOTAL (SM_BC + 256)               // 92928

// ---- device scratch ----
__device__ float4 g_acc[N_CUST];                 // {sum0, sum1, count, pad}
__device__ float  g_gf[N_FUND * 2];
__device__ float  g_A2[HID * 2];                 // W_l @ W_out
__device__ float  g_B2[HID * 2];                 // W_r @ W_out
__device__ float  g_c2[2];                       // b_l @ W_out + b_out
__device__ __nv_bfloat16 g_Bhi[HID * KP];        // W^T bf16 hi, [n][k]
__device__ __nv_bfloat16 g_Blo[HID * KP];        // W^T bf16 lo

__device__ __forceinline__ uint32_t smem_u32(const void* p) {
    uint32_t a;
    asm("{ .reg .u64 t; cvta.to.shared.u64 t, %1; cvt.u32.u64 %0, t; }" : "=r"(a) : "l"(p));
    return a;
}
#define LDMX4(r0, r1, r2, r3, addr) \
    asm volatile("ldmatrix.sync.aligned.m8n8.x4.shared.b16 {%0,%1,%2,%3}, [%4];" \
                 : "=r"(r0), "=r"(r1), "=r"(r2), "=r"(r3) : "r"(addr))
#define MMA_BF16(d, a0, a1, a2, a3, b0, b1) \
    asm volatile("mma.sync.aligned.m16n8k16.row.col.f32.bf16.bf16.f32 " \
                 "{%0,%1,%2,%3}, {%4,%5,%6,%7}, {%8,%9}, {%0,%1,%2,%3};" \
                 : "+f"((d)[0]), "+f"((d)[1]), "+f"((d)[2]), "+f"((d)[3]) \
                 : "r"(a0), "r"(a1), "r"(a2), "r"(a3), "r"(b0), "r"(b1))

// ================= prep kernels =================
__global__ void combine_weights_kernel(const float* __restrict__ W_l,
                                       const float* __restrict__ b_l,
                                       const float* __restrict__ W_r,
                                       const float* __restrict__ W_out,
                                       const float* __restrict__ b_out) {
    int t = threadIdx.x;
    if (t < HID * 2) {
        int k = t >> 1, j = t & 1;
        float a = 0.f, b = 0.f;
        #pragma unroll
        for (int h = 0; h < HID; h++) {
            a += W_l[k * HID + h] * W_out[h * 2 + j];
            b += W_r[k * HID + h] * W_out[h * 2 + j];
        }
        g_A2[k * 2 + j] = a;
        g_B2[k * 2 + j] = b;
    }
    if (t < 2) {
        float c = b_out[t];
        #pragma unroll
        for (int h = 0; h < HID; h++) c += b_l[h] * W_out[h * 2 + t];
        g_c2[t] = c;
    }
}

__global__ void wsplit_kernel(const float* __restrict__ W_cust) {
    int idx = blockIdx.x * blockDim.x + threadIdx.x;
    if (idx >= HID * KP) return;
    int n = idx / KP, k = idx - n * KP;
    float w = (k < D_CUST) ? W_cust[k * HID + n] : 0.f;
    __nv_bfloat16 h = __float2bfloat16(w);
    g_Bhi[idx] = h;
    g_Blo[idx] = __float2bfloat16(w - __bfloat162float(h));
}

__global__ void zero_kernel() {
    int i = blockIdx.x * blockDim.x + threadIdx.x;
    if (i < N_CUST) g_acc[i] = make_float4(0.f, 0.f, 0.f, 0.f);
}

__global__ void fund_kernel(const float* __restrict__ x_fund,
                            const float* __restrict__ W_fund,
                            const float* __restrict__ b_fund) {
    __shared__ float sw[HID], sb[HID], sA[HID * 2];
    int t = threadIdx.x;
    if (t < HID) { sw[t] = W_fund[t]; sb[t] = b_fund[t]; }
    if (t < HID * 2) sA[t] = g_A2[t];
    __syncthreads();
    int j = blockIdx.x * blockDim.x + t;
    if (j >= N_FUND) return;
    float xv = x_fund[j];
    float a0 = 0.f, a1 = 0.f;
    #pragma unroll
    for (int h = 0; h < HID; h++) {
        float hv = fmaxf(xv * sw[h] + sb[h], 0.f);
        a0 += hv * sA[h * 2 + 0];
        a1 += hv * sA[h * 2 + 1];
    }
    reinterpret_cast<float2*>(g_gf)[j] = make_float2(a0, a1);
}

__global__ void edge_kernel(const int* __restrict__ src,
                            const int* __restrict__ dst) {
    int i = blockIdx.x * blockDim.x + threadIdx.x;
    if (i >= N_EDGE) return;
    int s = __ldg(&src[i]);
    int d = __ldg(&dst[i]);
    float2 g = reinterpret_cast<const float2*>(g_gf)[s];
    float4* p = &g_acc[d];
    asm volatile("red.global.add.v4.f32 [%0], {%1, %2, %3, %4};"
                 :: "l"(p), "f"(g.x), "f"(g.y), "f"(1.0f), "f"(0.0f)
                 : "memory");
}

// ================= customer kernel: HMMA bf16-split GEMM =================
__global__ void __launch_bounds__(CT)
cust_kernel(const float* __restrict__ x,
            const float* __restrict__ b_cust,
            float* __restrict__ out) {
    extern __shared__ __align__(256) char dsm[];
    const uint32_t sbase = smem_u32(dsm);
    const int tid  = threadIdx.x;
    const int wid  = tid >> 5;
    const int lane = tid & 31;
    const int base = blockIdx.x * TM;

    float* sB2 = reinterpret_cast<float*>(dsm + SM_B2);
    float* sBc = reinterpret_cast<float*>(dsm + SM_BC);

    // --- stage B (W^T hi/lo), B2, bias ---
    {
        const uint4* bh = reinterpret_cast<const uint4*>(g_Bhi);
        const uint4* bl = reinterpret_cast<const uint4*>(g_Blo);
        uint4* dh = reinterpret_cast<uint4*>(dsm + SM_BH);
        uint4* dl = reinterpret_cast<uint4*>(dsm + SM_BL);
        for (int i = tid; i < HID * KP * 2 / 16; i += CT) { dh[i] = bh[i]; dl[i] = bl[i]; }
    }
    if (tid < HID * 2) sB2[tid] = g_B2[tid];
    if (tid < HID) sBc[tid] = b_cust[tid];

    // --- stage A: x tile -> bf16 hi/lo [128][120] ---
    {
        __nv_bfloat16* ah = reinterpret_cast<__nv_bfloat16*>(dsm + SM_AH);
        __nv_bfloat16* al = reinterpret_cast<__nv_bfloat16*>(dsm + SM_AL);
        for (int idx = tid; idx < TM * KP; idx += CT) {
            int r = idx / KP, k = idx - r * KP;
            int row = base + r;
            float v = (row < N_CUST && k < D_CUST) ? __ldg(&x[(size_t)row * D_CUST + k]) : 0.f;
            __nv_bfloat16 h = __float2bfloat16(v);
            ah[idx] = h;
            al[idx] = __float2bfloat16(v - __bfloat162float(h));
        }
    }
    __syncthreads();

    // --- mainloop ---
    float acc[8][4];
    #pragma unroll
    for (int i = 0; i < 8; i++)
        #pragma unroll
        for (int j = 0; j < 4; j++) acc[i][j] = 0.f;

    const int m0 = wid * 16;
    const int r8  = lane & 7;
    const int sel = lane >> 3;
    // A ldmatrix address: blocks (m0-7,klo),(m8-15,klo),(m0-7,khi),(m8-15,khi)
    const uint32_t a_row = (uint32_t)(m0 + r8 + ((sel & 1) << 3));
    const uint32_t a_off = a_row * (KP * 2) + (uint32_t)((sel >> 1) << 4);
    const uint32_t aH = sbase + SM_AH + a_off;
    const uint32_t aL = sbase + SM_AL + a_off;
    // B ldmatrix address: blocks (n0-7,klo),(n0-7,khi),(n8-15,klo),(n8-15,khi)
    const uint32_t b_row = (uint32_t)(r8 + ((sel >> 1) << 3));
    const uint32_t b_off = b_row * (KP * 2) + (uint32_t)((sel & 1) << 4);
    const uint32_t bH = sbase + SM_BH + b_off;
    const uint32_t bL = sbase + SM_BL + b_off;

    #pragma unroll
    for (int kk = 0; kk < 7; kk++) {
        const uint32_t ka = (uint32_t)kk * 32u;
        uint32_t ah0, ah1, ah2, ah3, al0, al1, al2, al3;
        LDMX4(ah0, ah1, ah2, ah3, aH + ka);
        LDMX4(al0, al1, al2, al3, aL + ka);
        #pragma unroll
        for (int ntp = 0; ntp < 4; ntp++) {
            const uint32_t bo = (uint32_t)(ntp * 16) * (KP * 2) + ka;
            uint32_t h0, h1, h2, h3, l0, l1, l2, l3;
            LDMX4(h0, h1, h2, h3, bH + bo);
            LDMX4(l0, l1, l2, l3, bL + bo);
            MMA_BF16(acc[2 * ntp],     ah0, ah1, ah2, ah3, h0, h1);
            MMA_BF16(acc[2 * ntp],     ah0, ah1, ah2, ah3, l0, l1);
            MMA_BF16(acc[2 * ntp],     al0, al1, al2, al3, h0, h1);
            MMA_BF16(acc[2 * ntp + 1], ah0, ah1, ah2, ah3, h2, h3);
            MMA_BF16(acc[2 * ntp + 1], ah0, ah1, ah2, ah3, l2, l3);
            MMA_BF16(acc[2 * ntp + 1], al0, al1, al2, al3, h2, h3);
        }
    }

    // --- epilogue: bias + relu + head projection ---
    const int gid = lane >> 2, tig = lane & 3;
    float o00 = 0.f, o01 = 0.f, o10 = 0.f, o11 = 0.f;
    #pragma unroll
    for (int nt = 0; nt < 8; nt++) {
        int c0 = nt * 8 + 2 * tig, c1 = c0 + 1;
        float w00 = sB2[2 * c0], w01 = sB2[2 * c0 + 1];
        float w10 = sB2[2 * c1], w11 = sB2[2 * c1 + 1];
        float bc0 = sBc[c0], bc1 = sBc[c1];
        float v;
        v = fmaxf(acc[nt][0] + bc0, 0.f); o00 += v * w00; o01 += v * w01;
        v = fmaxf(acc[nt][1] + bc1, 0.f); o00 += v * w10; o01 += v * w11;
        v = fmaxf(acc[nt][2] + bc0, 0.f); o10 += v * w00; o11 += v * w01;
        v = fmaxf(acc[nt][3] + bc1, 0.f); o10 += v * w10; o11 += v * w11;
    }
    #pragma unroll
    for (int off = 1; off <= 2; off <<= 1) {
        o00 += __shfl_xor_sync(0xFFFFFFFFu, o00, off);
        o01 += __shfl_xor_sync(0xFFFFFFFFu, o01, off);
        o10 += __shfl_xor_sync(0xFFFFFFFFu, o10, off);
        o11 += __shfl_xor_sync(0xFFFFFFFFu, o11, off);
    }
    if (tig == 0) {
        const float c20 = g_c2[0], c21 = g_c2[1];
        int row = base + m0 + gid;
        if (row < N_CUST) {
            float4 a = g_acc[row];
            float inv = 1.0f / fmaxf(a.z, 1.0f);
            reinterpret_cast<float2*>(out)[row] =
                make_float2(a.x * inv + o00 + c20, a.y * inv + o01 + c21);
        }
        row += 8;
        if (row < N_CUST) {
            float4 a = g_acc[row];
            float inv = 1.0f / fmaxf(a.z, 1.0f);
            reinterpret_cast<float2*>(out)[row] =
                make_float2(a.x * inv + o10 + c20, a.y * inv + o11 + c21);
        }
    }
}

// ================= launch =================
extern "C" void kernel_launch(void* const* d_in, const int* in_sizes, int n_in,
                              void* d_out, int out_size) {
    const float* x_customer = (const float*)d_in[0];
    const float* x_fund     = (const float*)d_in[1];
    const int*   src_fund   = (const int*)d_in[2];
    const int*   dst_cust   = (const int*)d_in[3];
    const float* W_cust     = (const float*)d_in[4];
    const float* b_cust     = (const float*)d_in[5];
    const float* W_fund     = (const float*)d_in[6];
    const float* b_fund     = (const float*)d_in[7];
    const float* W_l        = (const float*)d_in[8];
    const float* b_l        = (const float*)d_in[9];
    const float* W_r        = (const float*)d_in[10];
    const float* W_out      = (const float*)d_in[11];
    const float* b_out      = (const float*)d_in[12];
    float* out = (float*)d_out;

    cudaFuncSetAttribute(cust_kernel,
                         cudaFuncAttributeMaxDynamicSharedMemorySize, SM_TOTAL);

    combine_weights_kernel<<<1, 128>>>(W_l, b_l, W_r, W_out, b_out);
    wsplit_kernel<<<(HID * KP + 255) / 256, 256>>>(W_cust);
    zero_kernel<<<(N_CUST + 255) / 256, 256>>>();
    fund_kernel<<<(N_FUND + 255) / 256, 256>>>(x_fund, W_fund, b_fund);
    edge_kernel<<<(N_EDGE + 255) / 256, 256>>>(src_fund, dst_cust);
    cust_kernel<<<(N_CUST + TM - 1) / TM, CT, SM_TOTAL>>>(x_customer, b_cust, out);
}